// round 12
// baseline (speedup 1.0000x reference)
#include <cuda_runtime.h>

// ============================================================================
// EqProp relaxation — round 10: int8 u8xs8 IMMA (de-risked round-5 variant).
//  - Layer-1 forward init (raw x @ W0) runs as a one-time fp32 SIMT GEMM
//    (exact; removes all signed-activation IMMA paths).
//  - Everything else: exact 16-bit fixed-point splits on u8xs8 IMMA.
//  states s in [0,1]: s16 = rn(s*65536) clamp 65535; sh = s16>>8 (u8), sl = s16&255 (u8)
//  weights (global scale SW): w16 = rn(w/SW) clamp ±32639;
//      wh = (w16+128)>>8 (s8), wl = ((w16+128)&255)-128 (s8)  [zero-mean lo]
//  GEMM: acc_hi += Sh*Wh ; acc_mid += Sh*Wl + Sl*Wh  (s32 IMMA m16n8k32)
//  dot = SW * (acc_hi + acc_mid/256)
// ============================================================================

#define BATCHN  1024
#define DHID    2048
#define DOUT    1000
#define DOUTP   1024
#define N_RELAX 25
#define LR      0.3f

#define SW_Q    (0.19f / 32768.0f)
#define INV_SW  (32768.0f / 0.19f)

#define LDS_B   80              // 64 data + 16 pad bytes per SMEM row
#define MATA    (128 * LDS_B)   // 10240 B per 128-row int8 tile

__device__ __forceinline__ unsigned smem_u32(const void* p) {
    unsigned a;
    asm("{ .reg .u64 t; cvta.to.shared.u64 t, %1; cvt.u32.u64 %0, t; }" : "=r"(a) : "l"(p));
    return a;
}

#define CP16(dst, src) asm volatile("cp.async.cg.shared.global [%0], [%1], 16;" :: "r"(dst), "l"(src) : "memory")
#define CP_COMMIT()    asm volatile("cp.async.commit_group;" ::: "memory")
#define CP_WAIT0()     asm volatile("cp.async.wait_group 0;" ::: "memory")

#define LDSM4(r, a) \
    asm volatile("ldmatrix.sync.aligned.m8n8.x4.shared.b16 {%0,%1,%2,%3}, [%4];" \
                 : "=r"((r)[0]), "=r"((r)[1]), "=r"((r)[2]), "=r"((r)[3]) : "r"(a))

#define IMMA_U8S8(c, a, b0, b1) \
    asm volatile("mma.sync.aligned.m16n8k32.row.col.s32.u8.s8.s32 " \
                 "{%0,%1,%2,%3},{%4,%5,%6,%7},{%8,%9},{%0,%1,%2,%3};" \
                 : "+r"((c)[0]), "+r"((c)[1]), "+r"((c)[2]), "+r"((c)[3]) \
                 : "r"((a)[0]), "r"((a)[1]), "r"((a)[2]), "r"((a)[3]), "r"(b0), "r"(b1))

// --- static device storage ---------------------------------------------------
#define MB 1048576u
__device__ unsigned char g_i8[66u * MB];
__device__ float g_f[6u * MB + 1024u * 1000u];

#define OFF_RXH  (0u)
#define OFF_RXL  (2u*MB)
#define OFF_S1H  (4u*MB)
#define OFF_S1L  (6u*MB)
#define OFF_S2H  (8u*MB)
#define OFF_S2L  (10u*MB)
#define OFF_S3H  (12u*MB)
#define OFF_S3L  (14u*MB)
#define OFF_S4H  (16u*MB)
#define OFF_S4L  (17u*MB)
#define OFF_WT0H (18u*MB)
#define OFF_WT0L (22u*MB)
#define OFF_WT1H (26u*MB)
#define OFF_WT1L (30u*MB)
#define OFF_WT2H (34u*MB)
#define OFF_WT2L (38u*MB)
#define OFF_WT3H (42u*MB)
#define OFF_WT3L (44u*MB)
#define OFF_W1H  (46u*MB)
#define OFF_W1L  (50u*MB)
#define OFF_W2H  (54u*MB)
#define OFF_W2L  (58u*MB)
#define OFF_W3H  (62u*MB)
#define OFF_W3L  (64u*MB)
#define OFF_S1F  (0u)
#define OFF_S2F  (2u*MB)
#define OFF_S3F  (4u*MB)
#define OFF_S4F  (6u*MB)

// --- quantization kernels ----------------------------------------------------
__global__ void quant_rx_kernel(const float* __restrict__ x,
                                unsigned char* rxh, unsigned char* rxl, int n) {
    int i = blockIdx.x * blockDim.x + threadIdx.x;
    if (i < n) {
        float c = fminf(fmaxf(x[i], 0.0f), 1.0f);
        int s16 = __float2int_rn(c * 65536.0f);
        if (s16 > 65535) s16 = 65535;
        rxh[i] = (unsigned char)(s16 >> 8);
        rxl[i] = (unsigned char)(s16 & 0xFF);
    }
}

__device__ __forceinline__ void quant_w(float v, unsigned char& oh, unsigned char& ol) {
    int w16 = __float2int_rn(v * INV_SW);
    w16 = max(-32639, min(32639, w16));
    int t = w16 + 128;
    oh = (unsigned char)((t >> 8) & 0xFF);          // s8 bits
    ol = (unsigned char)(((t & 255) - 128) & 0xFF); // s8 bits, zero-mean
}

__global__ void quant_w_direct(const float* __restrict__ W, int R, int C, int Cpad,
                               unsigned char* oh, unsigned char* ol) {
    int i = blockIdx.x * blockDim.x + threadIdx.x;
    if (i < R * Cpad) {
        int r = i / Cpad, c = i - r * Cpad;
        float v = (c < C) ? W[(size_t)r * C + c] : 0.0f;
        quant_w(v, oh[i], ol[i]);
    }
}

__global__ void quant_w_trans(const float* __restrict__ W, int R, int C, int Cpad,
                              unsigned char* oh, unsigned char* ol) {
    __shared__ float t[32][33];
    int r0 = blockIdx.x * 32;
    int c0 = blockIdx.y * 32;
    int tx = threadIdx.x, ty = threadIdx.y;  // (32, 8)
#pragma unroll
    for (int i = 0; i < 4; i++) {
        int r = r0 + ty + i * 8, c = c0 + tx;
        t[ty + i * 8][tx] = (c < C) ? W[(size_t)r * C + c] : 0.0f;
    }
    __syncthreads();
#pragma unroll
    for (int i = 0; i < 4; i++) {
        int c = c0 + ty + i * 8;
        int r = r0 + tx;
        if (c < Cpad)
            quant_w(t[tx][ty + i * 8], oh[(size_t)c * R + r], ol[(size_t)c * R + r]);
    }
}

// --- fp32 SIMT GEMM for layer-1 forward init (raw x @ W0; exact) -------------
// C = x[1024,2048] @ W0[2048,2048]; out = clip(C + b1); writes s1f + u8 splits.
__global__ void __launch_bounds__(256, 2)
init_gemm_f32(const float* __restrict__ A, const float* __restrict__ B,
              const float* __restrict__ bias,
              float* __restrict__ outf, unsigned char* __restrict__ outh,
              unsigned char* __restrict__ outl)
{
    const int K = DHID, N = DHID;
    __shared__ float As[8][128];
    __shared__ float Bs[8][128];
    const int tid = threadIdx.x;
    const int tr = tid >> 4, tc = tid & 15;
    const int m0 = blockIdx.y * 128;
    const int n0 = blockIdx.x * 128;

    float acc[8][8];
#pragma unroll
    for (int i = 0; i < 8; i++)
#pragma unroll
        for (int j = 0; j < 8; j++) acc[i][j] = 0.0f;

    const int a_row = tid >> 1, a_col = (tid & 1) * 4;
    const int b_row = tid >> 5, b_col = (tid & 31) * 4;

    for (int k0 = 0; k0 < K; k0 += 8) {
        float4 av = *reinterpret_cast<const float4*>(A + (size_t)(m0 + a_row) * K + k0 + a_col);
        As[a_col + 0][a_row] = av.x;
        As[a_col + 1][a_row] = av.y;
        As[a_col + 2][a_row] = av.z;
        As[a_col + 3][a_row] = av.w;
        float4 bv = *reinterpret_cast<const float4*>(B + (size_t)(k0 + b_row) * N + n0 + b_col);
        *reinterpret_cast<float4*>(&Bs[b_row][b_col]) = bv;
        __syncthreads();
#pragma unroll
        for (int kk = 0; kk < 8; kk++) {
            float ra[8], rb[8];
#pragma unroll
            for (int i = 0; i < 8; i++) ra[i] = As[kk][tr * 8 + i];
#pragma unroll
            for (int j = 0; j < 8; j++) rb[j] = Bs[kk][tc * 8 + j];
#pragma unroll
            for (int i = 0; i < 8; i++)
#pragma unroll
                for (int j = 0; j < 8; j++) acc[i][j] += ra[i] * rb[j];
        }
        __syncthreads();
    }

#pragma unroll
    for (int i = 0; i < 8; i++) {
        int m = m0 + tr * 8 + i;
#pragma unroll
        for (int j = 0; j < 8; j++) {
            int n = n0 + tc * 8 + j;
            float r = fminf(fmaxf(acc[i][j] + bias[n], 0.0f), 1.0f);
            outf[(size_t)m * DHID + n] = r;
            int s16 = __float2int_rn(r * 65536.0f);
            if (s16 > 65535) s16 = 65535;
            outh[(size_t)m * DHID + n] = (unsigned char)(s16 >> 8);
            outl[(size_t)m * DHID + n] = (unsigned char)(s16 & 0xFF);
        }
    }
}

// --- main int8 GEMM kernel ---------------------------------------------------
// C[m,n] = A1[M,K1] @ B1[Npad,K1]^T (+ A2[M,K2] @ B2[Npad,K2]^T)
// A u8 hi/lo, B s8 hi/lo. Warp layout 4x2 (warp tile 32 x BN/2).
template <int BN>
__global__ void __launch_bounds__(256, 1)
eqprop_gemm(const unsigned char* __restrict__ A1h, const unsigned char* __restrict__ A1l, int K1,
            const unsigned char* __restrict__ B1h, const unsigned char* __restrict__ B1l,
            const unsigned char* __restrict__ A2h, const unsigned char* __restrict__ A2l, int K2,
            const unsigned char* __restrict__ B2h, const unsigned char* __restrict__ B2l,
            const float* __restrict__ bias, const float* __restrict__ Sold,
            float* __restrict__ outf, unsigned char* __restrict__ outh,
            unsigned char* __restrict__ outl,
            int Nreal, int Npad, int mode)
{
    constexpr int WCOLS = BN / 2;
    constexpr int NT    = WCOLS / 8;
    constexpr int NPR   = NT / 2;
    constexpr int MATB  = BN * LDS_B;
    constexpr int OFF_AHs = 0;
    constexpr int OFF_ALs = MATA;
    constexpr int OFF_BHs = 2 * MATA;
    constexpr int OFF_BLs = 2 * MATA + MATB;
    constexpr int SS      = 2 * MATA + 2 * MATB;

    extern __shared__ char smem[];
    const unsigned sbase = smem_u32(smem);
    const int tid  = threadIdx.x;
    const int wid  = tid >> 5, lane = tid & 31;
    const int wm   = wid >> 1;
    const int wn   = wid & 1;
    const int m0   = blockIdx.y * 128;
    const int n0   = blockIdx.x * BN;

    int hi[2][NT][4], mid[2][NT][4];
#pragma unroll
    for (int i = 0; i < 2; i++)
#pragma unroll
        for (int j = 0; j < NT; j++)
#pragma unroll
            for (int q = 0; q < 4; q++) { hi[i][j][q] = 0; mid[i][j][q] = 0; }

    const int nch1 = K1 >> 6;
    const int nch2 = K2 >> 6;
    const int nch  = nch1 + nch2;

    auto issue_loads = [&](int c, int st) {
        const unsigned char *pah, *pal, *pbh, *pbl;
        int ld, k0;
        if (c < nch1) { pah = A1h; pal = A1l; pbh = B1h; pbl = B1l; ld = K1; k0 = c << 6; }
        else          { pah = A2h; pal = A2l; pbh = B2h; pbl = B2l; ld = K2; k0 = (c - nch1) << 6; }
        const unsigned stb = sbase + st * SS;
#pragma unroll
        for (int j = 0; j < 2; j++) {
            int v = (tid << 1) | j;
            int r = v >> 2, q = v & 3;
            unsigned soff = (unsigned)(r * LDS_B + q * 16);
            size_t goff = (size_t)(m0 + r) * ld + k0 + q * 16;
            CP16(stb + OFF_AHs + soff, pah + goff);
            CP16(stb + OFF_ALs + soff, pal + goff);
        }
#pragma unroll
        for (int v = tid; v < BN * 4; v += 256) {
            int r = v >> 2, q = v & 3;
            unsigned soff = (unsigned)(r * LDS_B + q * 16);
            size_t goff = (size_t)(n0 + r) * ld + k0 + q * 16;
            CP16(stb + OFF_BHs + soff, pbh + goff);
            CP16(stb + OFF_BLs + soff, pbl + goff);
        }
    };

    const int lt = lane >> 3;
    const int lr = lane & 7;
    const unsigned a_lane_off = (unsigned)((wm * 32 + (lt & 1) * 8 + lr) * LDS_B + (lt >> 1) * 16);
    const unsigned b_lane_off = (unsigned)((wn * WCOLS + (lt >> 1) * 8 + lr) * LDS_B + (lt & 1) * 16);

    issue_loads(0, 0);
    CP_COMMIT();

    for (int i = 0; i < nch; i++) {
        CP_WAIT0();
        __syncthreads();
        if (i + 1 < nch) { issue_loads(i + 1, (i + 1) & 1); CP_COMMIT(); }

        const unsigned stb = sbase + (i & 1) * SS;
        const unsigned sAh = stb + OFF_AHs + a_lane_off;
        const unsigned sAl = stb + OFF_ALs + a_lane_off;
        const unsigned sBh = stb + OFF_BHs + b_lane_off;
        const unsigned sBl = stb + OFF_BLs + b_lane_off;

#pragma unroll
        for (int ks = 0; ks < 2; ks++) {
            const unsigned kb = ks * 32;
            unsigned ah[2][4], al[2][4];
#pragma unroll
            for (int mt = 0; mt < 2; mt++) {
                LDSM4(ah[mt], sAh + mt * (16 * LDS_B) + kb);
                LDSM4(al[mt], sAl + mt * (16 * LDS_B) + kb);
            }
#pragma unroll
            for (int pr = 0; pr < NPR; pr++) {
                unsigned bh[4], bl[4];
                LDSM4(bh, sBh + pr * (16 * LDS_B) + kb);
                LDSM4(bl, sBl + pr * (16 * LDS_B) + kb);
#pragma unroll
                for (int mt = 0; mt < 2; mt++) {
#pragma unroll
                    for (int t = 0; t < 2; t++) {
                        const int nt = pr * 2 + t;
                        const int hx = t * 2;
                        IMMA_U8S8(hi[mt][nt],  ah[mt], bh[hx], bh[hx + 1]);
                        IMMA_U8S8(mid[mt][nt], ah[mt], bl[hx], bl[hx + 1]);
                        IMMA_U8S8(mid[mt][nt], al[mt], bh[hx], bh[hx + 1]);
                    }
                }
            }
        }
    }

    // ---- epilogue ----
#pragma unroll
    for (int mt = 0; mt < 2; mt++) {
#pragma unroll
        for (int nt = 0; nt < NT; nt++) {
            const int n = n0 + wn * WCOLS + nt * 8 + ((lane & 3) << 1);
#pragma unroll
            for (int half = 0; half < 2; half++) {
                const int m = m0 + wm * 32 + mt * 16 + (lane >> 2) + half * 8;
#pragma unroll
                for (int e = 0; e < 2; e++) {
                    const int nn = n + e;
                    const int q = half * 2 + e;
                    float v = fmaf((float)mid[mt][nt][q], 0.00390625f,
                                   (float)hi[mt][nt][q]) * SW_Q;
                    float r;
                    if (nn < Nreal) {
                        float bb = bias[nn];
                        if (mode == 0) {
                            r = v + bb;
                        } else {
                            float s = Sold[(size_t)m * Nreal + nn];
                            r = s + LR * (bb + v - s);
                        }
                        r = fminf(fmaxf(r, 0.0f), 1.0f);
                        outf[(size_t)m * Nreal + nn] = r;
                    } else {
                        r = 0.0f;
                    }
                    if (nn < Npad) {
                        int s16 = __float2int_rn(r * 65536.0f);
                        if (s16 > 65535) s16 = 65535;
                        outh[(size_t)m * Npad + nn] = (unsigned char)(s16 >> 8);
                        outl[(size_t)m * Npad + nn] = (unsigned char)(s16 & 0xFF);
                    }
                }
            }
        }
    }
}

// --- host orchestration ------------------------------------------------------
static void launch_gemm(const unsigned char* A1h, const unsigned char* A1l, int K1,
                        const unsigned char* B1h, const unsigned char* B1l,
                        const unsigned char* A2h, const unsigned char* A2l, int K2,
                        const unsigned char* B2h, const unsigned char* B2l,
                        const float* bias, const float* Sold,
                        float* outf, unsigned char* outh, unsigned char* outl,
                        int Nreal, int Npad, int mode)
{
    if (Npad == 2048) {
        constexpr int SSB = 2 * (2 * MATA + 2 * 128 * LDS_B);
        dim3 grid(Npad / 128, BATCHN / 128);
        eqprop_gemm<128><<<grid, 256, SSB>>>(A1h, A1l, K1, B1h, B1l, A2h, A2l, K2, B2h, B2l,
                                             bias, Sold, outf, outh, outl, Nreal, Npad, mode);
    } else {
        constexpr int SSB = 2 * (2 * MATA + 2 * 64 * LDS_B);
        dim3 grid(Npad / 64, BATCHN / 128);
        eqprop_gemm<64><<<grid, 256, SSB>>>(A1h, A1l, K1, B1h, B1l, A2h, A2l, K2, B2h, B2l,
                                            bias, Sold, outf, outh, outl, Nreal, Npad, mode);
    }
}

extern "C" void kernel_launch(void* const* d_in, const int* in_sizes, int n_in,
                              void* d_out, int out_size)
{
    const float* x  = (const float*)d_in[0];
    const float* W0 = (const float*)d_in[1];
    const float* W1 = (const float*)d_in[2];
    const float* W2 = (const float*)d_in[3];
    const float* W3 = (const float*)d_in[4];
    const float* b1 = (const float*)d_in[5];
    const float* b2 = (const float*)d_in[6];
    const float* b3 = (const float*)d_in[7];
    const float* b4 = (const float*)d_in[8];

    cudaFuncSetAttribute(eqprop_gemm<128>, cudaFuncAttributeMaxDynamicSharedMemorySize,
                         2 * (2 * MATA + 2 * 128 * LDS_B));
    cudaFuncSetAttribute(eqprop_gemm<64>, cudaFuncAttributeMaxDynamicSharedMemorySize,
                         2 * (2 * MATA + 2 * 64 * LDS_B));

    unsigned char* p;
    float* fp;
    cudaGetSymbolAddress((void**)&p, g_i8);
    cudaGetSymbolAddress((void**)&fp, g_f);

    unsigned char *rxh = p + OFF_RXH, *rxl = p + OFF_RXL;
    unsigned char *s1h = p + OFF_S1H, *s1l = p + OFF_S1L;
    unsigned char *s2h = p + OFF_S2H, *s2l = p + OFF_S2L;
    unsigned char *s3h = p + OFF_S3H, *s3l = p + OFF_S3L;
    unsigned char *s4h = p + OFF_S4H, *s4l = p + OFF_S4L;
    unsigned char *wt0h = p + OFF_WT0H, *wt0l = p + OFF_WT0L;
    unsigned char *wt1h = p + OFF_WT1H, *wt1l = p + OFF_WT1L;
    unsigned char *wt2h = p + OFF_WT2H, *wt2l = p + OFF_WT2L;
    unsigned char *wt3h = p + OFF_WT3H, *wt3l = p + OFF_WT3L;
    unsigned char *w1h = p + OFF_W1H, *w1l = p + OFF_W1L;
    unsigned char *w2h = p + OFF_W2H, *w2l = p + OFF_W2L;
    unsigned char *w3h = p + OFF_W3H, *w3l = p + OFF_W3L;
    float *s1f = fp + OFF_S1F, *s2f = fp + OFF_S2F, *s3f = fp + OFF_S3F, *s4f = fp + OFF_S4F;

    {
        int n = BATCHN * DHID;
        quant_rx_kernel<<<(n + 255) / 256, 256>>>(x, rxh, rxl, n);
    }
    dim3 tb(32, 8);
    quant_w_trans<<<dim3(DHID / 32, DHID / 32),  tb>>>(W0, DHID, DHID, DHID,  wt0h, wt0l);
    quant_w_trans<<<dim3(DHID / 32, DHID / 32),  tb>>>(W1, DHID, DHID, DHID,  wt1h, wt1l);
    quant_w_trans<<<dim3(DHID / 32, DHID / 32),  tb>>>(W2, DHID, DHID, DHID,  wt2h, wt2l);
    quant_w_trans<<<dim3(DHID / 32, DOUTP / 32), tb>>>(W3, DHID, DOUT, DOUTP, wt3h, wt3l);
    {
        int n = DHID * DHID;
        quant_w_direct<<<(n + 255) / 256, 256>>>(W1, DHID, DHID, DHID, w1h, w1l);
        quant_w_direct<<<(n + 255) / 256, 256>>>(W2, DHID, DHID, DHID, w2h, w2l);
        int n3 = DHID * DOUTP;
        quant_w_direct<<<(n3 + 255) / 256, 256>>>(W3, DHID, DOUT, DOUTP, w3h, w3l);
    }

    // ---- forward init ----
    // layer 1: RAW x @ W0 in exact fp32 (one-time, ~350us)
    init_gemm_f32<<<dim3(DHID / 128, BATCHN / 128), 256>>>(x, W0, b1, s1f, s1h, s1l);
    // layers 2-4: int8 path (states are u8-exact)
    launch_gemm(s1h, s1l, DHID, wt1h, wt1l, nullptr, nullptr, 0, nullptr, nullptr,
                b2, nullptr, s2f, s2h, s2l, DHID, DHID, 0);
    launch_gemm(s2h, s2l, DHID, wt2h, wt2l, nullptr, nullptr, 0, nullptr, nullptr,
                b3, nullptr, s3f, s3h, s3l, DHID, DHID, 0);
    launch_gemm(s3h, s3l, DHID, wt3h, wt3l, nullptr, nullptr, 0, nullptr, nullptr,
                b4, nullptr, s4f, s4h, s4l, DOUT, DOUTP, 0);

    // ---- 25 Gauss-Seidel sweeps ----
    for (int it = 0; it < N_RELAX; it++) {
        // l=1: rho(x)@W0 + s2@W1^T
        launch_gemm(rxh, rxl, DHID, wt0h, wt0l, s2h, s2l, DHID, w1h, w1l,
                    b1, s1f, s1f, s1h, s1l, DHID, DHID, 1);
        // l=2: s1@W1 + s3@W2^T
        launch_gemm(s1h, s1l, DHID, wt1h, wt1l, s3h, s3l, DHID, w2h, w2l,
                    b2, s2f, s2f, s2h, s2l, DHID, DHID, 1);
        // l=3: s2@W2 + s4@W3^T (K2 = 1024 padded; s4 pad cols are zero)
        launch_gemm(s2h, s2l, DHID, wt2h, wt2l, s4h, s4l, DOUTP, w3h, w3l,
                    b3, s3f, s3f, s3h, s3l, DHID, DHID, 1);
        // l=4: s3@W3
        float* out4 = (it == N_RELAX - 1) ? (float*)d_out : s4f;
        launch_gemm(s3h, s3l, DHID, wt3h, wt3l, nullptr, nullptr, 0, nullptr, nullptr,
                    b4, s4f, out4, s4h, s4l, DOUT, DOUTP, 1);
    }
}

// round 13
// speedup vs baseline: 2.4380x; 2.4380x over previous
#include <cuda_runtime.h>
#include <cuda_bf16.h>
#include <cstdint>

// ============================================================================
// EqProp relaxation — round 13: bf16 3-term HMMA (proven round-3 core) +
//   (a) rho(x)@W0 cached once (loop-invariant; was recomputed 25x)
//   (b) BN=64 kernel variant for the N=1024 layer-4 GEMMs (full 128-CTA wave)
// GEMM: D += Ah*Bh + Al*Bh + Ah*Bl  (fp32 accum; A,B split hi/lo bf16)
// A [M,K] row-major, B [Npad,K] row-major (K-major) -> mma row.col
// ============================================================================

#define BATCHN  1024
#define DHID    2048
#define DOUT    1000
#define DOUTP   1024
#define N_RELAX 25
#define LR      0.3f

#define LDS_B   80                  // (32+8) bf16 per SMEM row
#define MAT_A_B (128 * LDS_B)       // 10240 B per 128-row matrix tile

__device__ __forceinline__ uint32_t smem_u32(const void* p) {
    uint32_t a;
    asm("{ .reg .u64 t; cvta.to.shared.u64 t, %1; cvt.u32.u64 %0, t; }" : "=r"(a) : "l"(p));
    return a;
}

#define CP16(dst, src) asm volatile("cp.async.cg.shared.global [%0], [%1], 16;" :: "r"(dst), "l"(src) : "memory")
#define CP_COMMIT()    asm volatile("cp.async.commit_group;" ::: "memory")
#define CP_WAIT0()     asm volatile("cp.async.wait_group 0;" ::: "memory")

#define LDSM4(r, a) \
    asm volatile("ldmatrix.sync.aligned.m8n8.x4.shared.b16 {%0,%1,%2,%3}, [%4];" \
                 : "=r"((r)[0]), "=r"((r)[1]), "=r"((r)[2]), "=r"((r)[3]) : "r"(a))

#define MMA16816(c, a, b0, b1) \
    asm volatile("mma.sync.aligned.m16n8k16.row.col.f32.bf16.bf16.f32 " \
                 "{%0,%1,%2,%3},{%4,%5,%6,%7},{%8,%9},{%0,%1,%2,%3};" \
                 : "+f"((c)[0]), "+f"((c)[1]), "+f"((c)[2]), "+f"((c)[3]) \
                 : "r"((a)[0]), "r"((a)[1]), "r"((a)[2]), "r"((a)[3]), "r"(b0), "r"(b1))

// --- static device storage ---------------------------------------------------
#define MEL 1048576
__device__ __nv_bfloat16 g_bf[70u * MEL];
__device__ float g_f[8u * MEL + 1024u * 1000u];

#define OFF_XH   (0u)
#define OFF_XL   (2u*MEL)
#define OFF_RXH  (4u*MEL)
#define OFF_RXL  (6u*MEL)
#define OFF_S1H  (8u*MEL)
#define OFF_S1L  (10u*MEL)
#define OFF_S2H  (12u*MEL)
#define OFF_S2L  (14u*MEL)
#define OFF_S3H  (16u*MEL)
#define OFF_S3L  (18u*MEL)
#define OFF_S4H  (20u*MEL)
#define OFF_S4L  (21u*MEL)
#define OFF_WT0H (22u*MEL)
#define OFF_WT0L (26u*MEL)
#define OFF_WT1H (30u*MEL)
#define OFF_WT1L (34u*MEL)
#define OFF_WT2H (38u*MEL)
#define OFF_WT2L (42u*MEL)
#define OFF_WT3H (46u*MEL)
#define OFF_WT3L (48u*MEL)
#define OFF_W1H  (50u*MEL)
#define OFF_W1L  (54u*MEL)
#define OFF_W2H  (58u*MEL)
#define OFF_W2L  (62u*MEL)
#define OFF_W3H  (66u*MEL)
#define OFF_W3L  (68u*MEL)
// float pool offsets
#define OFF_S1F  (0u)
#define OFF_S2F  (2u*MEL)
#define OFF_S3F  (4u*MEL)
#define OFF_CXF  (6u*MEL)     // cached rho(x)@W0, 1024x2048 fp32
#define OFF_S4F  (8u*MEL)     // 1024x1000

// --- conversion kernels ------------------------------------------------------
__device__ __forceinline__ void split2(float v, __nv_bfloat16& h, __nv_bfloat16& l) {
    h = __float2bfloat16(v);
    l = __float2bfloat16(v - __bfloat162float(h));
}

__global__ void convert_x_kernel(const float* __restrict__ x,
                                 __nv_bfloat16* xh, __nv_bfloat16* xl,
                                 __nv_bfloat16* rxh, __nv_bfloat16* rxl, int n) {
    int i = blockIdx.x * blockDim.x + threadIdx.x;
    if (i < n) {
        float v = x[i];
        __nv_bfloat16 h, l;
        split2(v, h, l); xh[i] = h; xl[i] = l;
        float c = fminf(fmaxf(v, 0.0f), 1.0f);
        split2(c, h, l); rxh[i] = h; rxl[i] = l;
    }
}

__global__ void convert_w_kernel(const float* __restrict__ W, int R, int C, int Cpad,
                                 __nv_bfloat16* oh, __nv_bfloat16* ol) {
    int i = blockIdx.x * blockDim.x + threadIdx.x;
    if (i < R * Cpad) {
        int r = i / Cpad, c = i - r * Cpad;
        float v = (c < C) ? W[(size_t)r * C + c] : 0.0f;
        __nv_bfloat16 h, l;
        split2(v, h, l); oh[i] = h; ol[i] = l;
    }
}

__global__ void transpose_w_kernel(const float* __restrict__ W, int R, int C, int Cpad,
                                   __nv_bfloat16* oh, __nv_bfloat16* ol) {
    __shared__ float t[32][33];
    int r0 = blockIdx.x * 32;
    int c0 = blockIdx.y * 32;
    int tx = threadIdx.x, ty = threadIdx.y;
#pragma unroll
    for (int i = 0; i < 4; i++) {
        int r = r0 + ty + i * 8, c = c0 + tx;
        t[ty + i * 8][tx] = (c < C) ? W[(size_t)r * C + c] : 0.0f;
    }
    __syncthreads();
#pragma unroll
    for (int i = 0; i < 4; i++) {
        int c = c0 + ty + i * 8;
        int r = r0 + tx;
        if (c < Cpad) {
            float v = t[tx][ty + i * 8];
            __nv_bfloat16 h, l;
            split2(v, h, l);
            oh[(size_t)c * R + r] = h;
            ol[(size_t)c * R + r] = l;
        }
    }
}

// --- main GEMM kernel (round-3 core, templated on BN; modes 0/1/3) ----------
// mode 0: out = clip(acc + add + bias)
// mode 1: s = Sold; out = clip(s + LR*(bias + acc + add - s))
// mode 3: outf = acc  (raw product store; no bias/clip/splits)
template <int BN>
__global__ void __launch_bounds__(256, 1)
eqprop_gemm(const __nv_bfloat16* __restrict__ A1h, const __nv_bfloat16* __restrict__ A1l, int K1,
            const __nv_bfloat16* __restrict__ B1h, const __nv_bfloat16* __restrict__ B1l,
            const __nv_bfloat16* __restrict__ A2h, const __nv_bfloat16* __restrict__ A2l, int K2,
            const __nv_bfloat16* __restrict__ B2h, const __nv_bfloat16* __restrict__ B2l,
            const float* __restrict__ bias, const float* __restrict__ Sold,
            const float* __restrict__ addf,
            float* __restrict__ outf, __nv_bfloat16* __restrict__ outh,
            __nv_bfloat16* __restrict__ outl,
            int Nreal, int Npad, int mode)
{
    constexpr int WCOLS = BN / 4;         // per-warp cols: 32 (BN=128) / 16 (BN=64)
    constexpr int NT    = WCOLS / 8;      // 4 / 2
    constexpr int NPR   = NT / 2;         // 2 / 1
    constexpr int MATB  = BN * LDS_B;
    constexpr int OFF_AH = 0;
    constexpr int OFF_AL = MAT_A_B;
    constexpr int OFF_BH = 2 * MAT_A_B;
    constexpr int OFF_BL = 2 * MAT_A_B + MATB;
    constexpr int SS     = 2 * MAT_A_B + 2 * MATB;

    extern __shared__ char smem[];
    const uint32_t sbase = smem_u32(smem);
    const int tid  = threadIdx.x;
    const int wid  = tid >> 5, lane = tid & 31;
    const int wm   = wid >> 2;          // 0..1 (64 rows each)
    const int wn   = wid & 3;           // 0..3 (WCOLS cols each)
    const int m0   = blockIdx.y * 128;
    const int n0   = blockIdx.x * BN;

    float acc[4][NT][4];
#pragma unroll
    for (int i = 0; i < 4; i++)
#pragma unroll
        for (int j = 0; j < NT; j++)
#pragma unroll
            for (int q = 0; q < 4; q++) acc[i][j][q] = 0.0f;

    const int nch1 = K1 >> 5;
    const int nch2 = K2 >> 5;
    const int nch  = nch1 + nch2;

    auto issue_loads = [&](int c, int st) {
        const __nv_bfloat16 *pah, *pal, *pbh, *pbl;
        int ld, k0;
        if (c < nch1) { pah = A1h; pal = A1l; pbh = B1h; pbl = B1l; ld = K1; k0 = c << 5; }
        else          { pah = A2h; pal = A2l; pbh = B2h; pbl = B2l; ld = K2; k0 = (c - nch1) << 5; }
        const uint32_t stb = sbase + st * SS;
        // A hi/lo: 128 rows x 64B = 512 x 16B ops, 2/thread each
#pragma unroll
        for (int j = 0; j < 2; j++) {
            int v = (tid << 1) | j;
            int r = v >> 2, q = v & 3;
            uint32_t soff = (uint32_t)(r * LDS_B + q * 16);
            size_t goff = (size_t)(m0 + r) * ld + k0 + q * 8;
            CP16(stb + OFF_AH + soff, pah + goff);
            CP16(stb + OFF_AL + soff, pal + goff);
        }
        // B hi/lo: BN rows x 64B = BN*4 x 16B ops
#pragma unroll
        for (int v = tid; v < BN * 4; v += 256) {
            int r = v >> 2, q = v & 3;
            uint32_t soff = (uint32_t)(r * LDS_B + q * 16);
            size_t goff = (size_t)(n0 + r) * ld + k0 + q * 8;
            CP16(stb + OFF_BH + soff, pbh + goff);
            CP16(stb + OFF_BL + soff, pbl + goff);
        }
    };

    const int lt = lane >> 3;
    const int lr = lane & 7;
    const uint32_t a_lane_off = (uint32_t)((wm * 64 + (lt & 1) * 8 + lr) * LDS_B + (lt >> 1) * 16);
    const uint32_t b_lane_off = (uint32_t)((wn * WCOLS + (lt >> 1) * 8 + lr) * LDS_B + (lt & 1) * 16);

    issue_loads(0, 0);
    CP_COMMIT();

    for (int i = 0; i < nch; i++) {
        CP_WAIT0();
        __syncthreads();
        if (i + 1 < nch) { issue_loads(i + 1, (i + 1) & 1); CP_COMMIT(); }

        const uint32_t stb = sbase + (i & 1) * SS;
        const uint32_t sAh = stb + OFF_AH + a_lane_off;
        const uint32_t sAl = stb + OFF_AL + a_lane_off;
        const uint32_t sBh = stb + OFF_BH + b_lane_off;
        const uint32_t sBl = stb + OFF_BL + b_lane_off;

#pragma unroll
        for (int k16 = 0; k16 < 2; k16++) {
            const uint32_t kb = k16 * 32;
            uint32_t ah[4][4], al[4][4];
#pragma unroll
            for (int mt = 0; mt < 4; mt++) {
                LDSM4(ah[mt], sAh + mt * (16 * LDS_B) + kb);
                LDSM4(al[mt], sAl + mt * (16 * LDS_B) + kb);
            }
            uint32_t bh[NPR][4], bl[NPR][4];
#pragma unroll
            for (int pr = 0; pr < NPR; pr++) {
                LDSM4(bh[pr], sBh + pr * (16 * LDS_B) + kb);
                LDSM4(bl[pr], sBl + pr * (16 * LDS_B) + kb);
            }
#pragma unroll
            for (int mt = 0; mt < 4; mt++) {
#pragma unroll
                for (int nt = 0; nt < NT; nt++) {
                    const int pr = nt >> 1, hx = (nt & 1) * 2;
                    MMA16816(acc[mt][nt], ah[mt], bh[pr][hx], bh[pr][hx + 1]);
                    MMA16816(acc[mt][nt], al[mt], bh[pr][hx], bh[pr][hx + 1]);
                    MMA16816(acc[mt][nt], ah[mt], bl[pr][hx], bl[pr][hx + 1]);
                }
            }
        }
        __syncthreads();
    }

    // ---- epilogue ----
#pragma unroll
    for (int mt = 0; mt < 4; mt++) {
#pragma unroll
        for (int nt = 0; nt < NT; nt++) {
            const int n = n0 + wn * WCOLS + nt * 8 + ((lane & 3) << 1);
#pragma unroll
            for (int half = 0; half < 2; half++) {
                const int m = m0 + wm * 64 + mt * 16 + (lane >> 2) + half * 8;
#pragma unroll
                for (int e = 0; e < 2; e++) {
                    const int nn = n + e;
                    float v = acc[mt][nt][half * 2 + e];
                    if (mode == 3) {
                        if (nn < Nreal) outf[(size_t)m * Nreal + nn] = v;
                        continue;
                    }
                    float r;
                    if (nn < Nreal) {
                        if (addf) v += addf[(size_t)m * Nreal + nn];
                        float bb = bias[nn];
                        if (mode == 0) {
                            r = v + bb;
                        } else {
                            float s = Sold[(size_t)m * Nreal + nn];
                            r = s + LR * (bb + v - s);
                        }
                        r = fminf(fmaxf(r, 0.0f), 1.0f);
                        outf[(size_t)m * Nreal + nn] = r;
                    } else {
                        r = 0.0f;
                    }
                    if (nn < Npad) {
                        __nv_bfloat16 h, l;
                        split2(r, h, l);
                        outh[(size_t)m * Npad + nn] = h;
                        outl[(size_t)m * Npad + nn] = l;
                    }
                }
            }
        }
    }
}

// --- host orchestration ------------------------------------------------------
static void launch_gemm(const __nv_bfloat16* A1h, const __nv_bfloat16* A1l, int K1,
                        const __nv_bfloat16* B1h, const __nv_bfloat16* B1l,
                        const __nv_bfloat16* A2h, const __nv_bfloat16* A2l, int K2,
                        const __nv_bfloat16* B2h, const __nv_bfloat16* B2l,
                        const float* bias, const float* Sold, const float* addf,
                        float* outf, __nv_bfloat16* outh, __nv_bfloat16* outl,
                        int Nreal, int Npad, int mode)
{
    if (Npad == 2048) {
        constexpr int SSB = 2 * (2 * MAT_A_B + 2 * 128 * LDS_B);
        dim3 grid(Npad / 128, BATCHN / 128);
        eqprop_gemm<128><<<grid, 256, SSB>>>(A1h, A1l, K1, B1h, B1l, A2h, A2l, K2, B2h, B2l,
                                             bias, Sold, addf, outf, outh, outl, Nreal, Npad, mode);
    } else {
        constexpr int SSB = 2 * (2 * MAT_A_B + 2 * 64 * LDS_B);
        dim3 grid(Npad / 64, BATCHN / 128);
        eqprop_gemm<64><<<grid, 256, SSB>>>(A1h, A1l, K1, B1h, B1l, A2h, A2l, K2, B2h, B2l,
                                            bias, Sold, addf, outf, outh, outl, Nreal, Npad, mode);
    }
}

extern "C" void kernel_launch(void* const* d_in, const int* in_sizes, int n_in,
                              void* d_out, int out_size)
{
    const float* x  = (const float*)d_in[0];
    const float* W0 = (const float*)d_in[1];
    const float* W1 = (const float*)d_in[2];
    const float* W2 = (const float*)d_in[3];
    const float* W3 = (const float*)d_in[4];
    const float* b1 = (const float*)d_in[5];
    const float* b2 = (const float*)d_in[6];
    const float* b3 = (const float*)d_in[7];
    const float* b4 = (const float*)d_in[8];

    cudaFuncSetAttribute(eqprop_gemm<128>, cudaFuncAttributeMaxDynamicSharedMemorySize,
                         2 * (2 * MAT_A_B + 2 * 128 * LDS_B));
    cudaFuncSetAttribute(eqprop_gemm<64>, cudaFuncAttributeMaxDynamicSharedMemorySize,
                         2 * (2 * MAT_A_B + 2 * 64 * LDS_B));

    __nv_bfloat16* bf;
    float* fp;
    cudaGetSymbolAddress((void**)&bf, g_bf);
    cudaGetSymbolAddress((void**)&fp, g_f);

    __nv_bfloat16 *xh = bf + OFF_XH,  *xl = bf + OFF_XL;
    __nv_bfloat16 *rxh = bf + OFF_RXH, *rxl = bf + OFF_RXL;
    __nv_bfloat16 *s1h = bf + OFF_S1H, *s1l = bf + OFF_S1L;
    __nv_bfloat16 *s2h = bf + OFF_S2H, *s2l = bf + OFF_S2L;
    __nv_bfloat16 *s3h = bf + OFF_S3H, *s3l = bf + OFF_S3L;
    __nv_bfloat16 *s4h = bf + OFF_S4H, *s4l = bf + OFF_S4L;
    __nv_bfloat16 *wt0h = bf + OFF_WT0H, *wt0l = bf + OFF_WT0L;
    __nv_bfloat16 *wt1h = bf + OFF_WT1H, *wt1l = bf + OFF_WT1L;
    __nv_bfloat16 *wt2h = bf + OFF_WT2H, *wt2l = bf + OFF_WT2L;
    __nv_bfloat16 *wt3h = bf + OFF_WT3H, *wt3l = bf + OFF_WT3L;
    __nv_bfloat16 *w1h = bf + OFF_W1H, *w1l = bf + OFF_W1L;
    __nv_bfloat16 *w2h = bf + OFF_W2H, *w2l = bf + OFF_W2L;
    __nv_bfloat16 *w3h = bf + OFF_W3H, *w3l = bf + OFF_W3L;
    float *s1f = fp + OFF_S1F, *s2f = fp + OFF_S2F, *s3f = fp + OFF_S3F;
    float *cxf = fp + OFF_CXF, *s4f = fp + OFF_S4F;

    {
        int n = BATCHN * DHID;
        convert_x_kernel<<<(n + 255) / 256, 256>>>(x, xh, xl, rxh, rxl, n);
    }
    dim3 tb(32, 8);
    transpose_w_kernel<<<dim3(DHID / 32, DHID / 32),  tb>>>(W0, DHID, DHID, DHID,  wt0h, wt0l);
    transpose_w_kernel<<<dim3(DHID / 32, DHID / 32),  tb>>>(W1, DHID, DHID, DHID,  wt1h, wt1l);
    transpose_w_kernel<<<dim3(DHID / 32, DHID / 32),  tb>>>(W2, DHID, DHID, DHID,  wt2h, wt2l);
    transpose_w_kernel<<<dim3(DHID / 32, DOUTP / 32), tb>>>(W3, DHID, DOUT, DOUTP, wt3h, wt3l);
    {
        int n = DHID * DHID;
        convert_w_kernel<<<(n + 255) / 256, 256>>>(W1, DHID, DHID, DHID, w1h, w1l);
        convert_w_kernel<<<(n + 255) / 256, 256>>>(W2, DHID, DHID, DHID, w2h, w2l);
        int n3 = DHID * DOUTP;
        convert_w_kernel<<<(n3 + 255) / 256, 256>>>(W3, DHID, DOUT, DOUTP, w3h, w3l);
    }

    // ---- forward init (layer 1 uses RAW x) ----
    launch_gemm(xh,  xl,  DHID, wt0h, wt0l, nullptr, nullptr, 0, nullptr, nullptr,
                b1, nullptr, nullptr, s1f, s1h, s1l, DHID, DHID, 0);
    launch_gemm(s1h, s1l, DHID, wt1h, wt1l, nullptr, nullptr, 0, nullptr, nullptr,
                b2, nullptr, nullptr, s2f, s2h, s2l, DHID, DHID, 0);
    launch_gemm(s2h, s2l, DHID, wt2h, wt2l, nullptr, nullptr, 0, nullptr, nullptr,
                b3, nullptr, nullptr, s3f, s3h, s3l, DHID, DHID, 0);
    launch_gemm(s3h, s3l, DHID, wt3h, wt3l, nullptr, nullptr, 0, nullptr, nullptr,
                b4, nullptr, nullptr, s4f, s4h, s4l, DOUT, DOUTP, 0);

    // ---- cache the loop-invariant rho(x)@W0 (raw fp32 product) ----
    launch_gemm(rxh, rxl, DHID, wt0h, wt0l, nullptr, nullptr, 0, nullptr, nullptr,
                b1, nullptr, nullptr, cxf, s1h /*unused*/, s1l /*unused*/, DHID, DHID, 3);

    // ---- 25 Gauss-Seidel sweeps ----
    for (int it = 0; it < N_RELAX; it++) {
        // l=1: cached rho(x)@W0 + s2@W1^T   (single NT GEMM + epilogue add)
        launch_gemm(s2h, s2l, DHID, w1h, w1l, nullptr, nullptr, 0, nullptr, nullptr,
                    b1, s1f, cxf, s1f, s1h, s1l, DHID, DHID, 1);
        // l=2: s1@W1 + s3@W2^T
        launch_gemm(s1h, s1l, DHID, wt1h, wt1l, s3h, s3l, DHID, w2h, w2l,
                    b2, s2f, nullptr, s2f, s2h, s2l, DHID, DHID, 1);
        // l=3: s2@W2 + s4@W3^T  (K2 padded to 1024; s4 pad cols are zero)
        launch_gemm(s2h, s2l, DHID, wt2h, wt2l, s4h, s4l, DOUTP, w3h, w3l,
                    b3, s3f, nullptr, s3f, s3h, s3l, DHID, DHID, 1);
        // l=4: s3@W3  (BN=64 variant -> full 128-CTA wave)
        float* out4 = (it == N_RELAX - 1) ? (float*)d_out : s4f;
        launch_gemm(s3h, s3l, DHID, wt3h, wt3l, nullptr, nullptr, 0, nullptr, nullptr,
                    b4, s4f, nullptr, out4, s4h, s4l, DOUT, DOUTP, 1);
    }
}